// round 7
// baseline (speedup 1.0000x reference)
#include <cuda_runtime.h>
#include <cuda_bf16.h>
#include <cstdint>

#define NN 8192
#define DD 512
#define INV_T 25.0f
#define EPS_KOLEO 1e-9f

// ------------------- device scratch -------------------
__device__ __nv_bfloat16 g_zb1[NN * DD];
__device__ __nv_bfloat16 g_zb2[NN * DD];
__device__ float g_rowsum[NN];
__device__ float g_colsum[NN];
__device__ float g_diag[NN];
__device__ int   g_max1[NN];
__device__ int   g_max2[NN];

// ------------------- helpers -------------------
__device__ __forceinline__ int enc_f(float f) {
    int i = __float_as_int(f);
    return i >= 0 ? i : i ^ 0x7FFFFFFF;
}
__device__ __forceinline__ float dec_f(int i) {
    return __int_as_float(i >= 0 ? i : i ^ 0x7FFFFFFF);
}
__device__ __forceinline__ uint32_t smem_u32(const void* p) {
    uint32_t a;
    asm("{ .reg .u64 t; cvta.to.shared.u64 t, %1; cvt.u32.u64 %0, t; }"
        : "=r"(a) : "l"(p));
    return a;
}
__device__ __forceinline__ void cp16(uint32_t saddr, const void* g) {
    asm volatile("cp.async.cg.shared.global [%0], [%1], 16;" :: "r"(saddr), "l"(g));
}
__device__ __forceinline__ void cp_commit() {
    asm volatile("cp.async.commit_group;" ::: "memory");
}
__device__ __forceinline__ void cp_wait1() {
    asm volatile("cp.async.wait_group 1;" ::: "memory");
}
__device__ __forceinline__ void cp_wait0() {
    asm volatile("cp.async.wait_group 0;" ::: "memory");
}
__device__ __forceinline__ void ldsm_x4(uint32_t* r, uint32_t a) {
    asm volatile("ldmatrix.sync.aligned.m8n8.x4.shared.b16 {%0,%1,%2,%3}, [%4];"
                 : "=r"(r[0]), "=r"(r[1]), "=r"(r[2]), "=r"(r[3]) : "r"(a));
}
__device__ __forceinline__ void mma_bf16(float* c, const uint32_t* a, const uint32_t* b) {
    asm volatile(
        "mma.sync.aligned.m16n8k16.row.col.f32.bf16.bf16.f32 "
        "{%0,%1,%2,%3}, {%4,%5,%6,%7}, {%8,%9}, {%0,%1,%2,%3};"
        : "+f"(c[0]), "+f"(c[1]), "+f"(c[2]), "+f"(c[3])
        : "r"(a[0]), "r"(a[1]), "r"(a[2]), "r"(a[3]), "r"(b[0]), "r"(b[1]));
}

// ------------------- normalization -> bf16 -------------------
__global__ void normalize_kernel(const float* __restrict__ z1,
                                 const float* __restrict__ z2) {
    int row = blockIdx.x;
    const float* src = blockIdx.y ? z2 : z1;
    __nv_bfloat16* dst = blockIdx.y ? g_zb2 : g_zb1;
    int t = threadIdx.x;  // 128 threads x 4 floats
    float4 v = ((const float4*)(src + (size_t)row * DD))[t];
    float s = v.x * v.x + v.y * v.y + v.z * v.z + v.w * v.w;
#pragma unroll
    for (int o = 16; o; o >>= 1) s += __shfl_xor_sync(0xffffffffu, s, o);
    __shared__ float ws[4];
    if ((t & 31) == 0) ws[t >> 5] = s;
    __syncthreads();
    float tot = ws[0] + ws[1] + ws[2] + ws[3];
    float scale = 1.0f / fmaxf(sqrtf(tot), 1e-12f);
    __nv_bfloat162 p0 = __floats2bfloat162_rn(v.x * scale, v.y * scale);
    __nv_bfloat162 p1 = __floats2bfloat162_rn(v.z * scale, v.w * scale);
    __nv_bfloat162* d = (__nv_bfloat162*)(dst + (size_t)row * DD);
    d[t * 2 + 0] = p0;
    d[t * 2 + 1] = p1;
}

__global__ void init_kernel() {
    int i = blockIdx.x * blockDim.x + threadIdx.x;
    if (i < NN) {
        g_colsum[i] = 0.0f;
        g_diag[i] = 0.0f;
        int e = enc_f(-2.0f);
        g_max1[i] = e;
        g_max2[i] = e;
    }
}

// =====================================================================
// A-stationary fused GEMM. 128 CTAs x 256 threads.
//   CTA 0..63:    mode 0 (cross z1@z2^T), bi = cta, 32 strips of N=256
//   CTA 64..95:   mode 1 (gram z1), row pair (g, 63-g), 33 strips total
//   CTA 96..127:  mode 2 (gram z2), same pairing
// A block (128 rows x K=512) resident in smem (16 slabs of 80B-pitch),
// B streamed in BK=32 chunks, 3-stage ring, depth-2 cp.async prefetch.
// 8 warps (2x4), warp tile 64x64, acc in regs; rows private to CTA.
// =====================================================================
#define PITCH 80
#define A_SLAB (128 * PITCH)             // 10240
#define A_TOTAL (16 * A_SLAB)            // 163840
#define B_STAGE (256 * PITCH)            // 20480
#define SMEM_DYN (A_TOTAL + 3 * B_STAGE) // 225280

__global__ __launch_bounds__(256, 1) void gemm_all() {
    const int cta = blockIdx.x;
    int njobs, jmode, jbi[2], jns[2];
    if (cta < 64) {
        njobs = 1; jmode = 0; jbi[0] = cta; jns[0] = 32;
    } else {
        int g = (cta - 64) & 31;
        jmode = (cta < 96) ? 1 : 2;
        njobs = 2;
        jbi[0] = g;      jns[0] = (g + 2) >> 1;
        jbi[1] = 63 - g; jns[1] = (65 - g) >> 1;
    }

    extern __shared__ __align__(16) char smem[];
    __shared__ int srow[128];            // per-job row accumulator (f32 or enc-int)
    __shared__ int scol[256];            // per-strip column accumulator

    const int tid = threadIdx.x;         // 256
    const int wid = tid >> 5;            // 0..7
    const int lane = tid & 31;
    const int wm = (wid >> 2) * 64;      // warp row offset (0/64)
    const int wn = (wid & 3) * 64;       // warp col offset (0..192)

    const uint32_t sdyn = smem_u32(smem);

    // lane-constant ldmatrix offsets (slab/stage relative)
    const uint32_t aOff = (wm + (lane & 15)) * PITCH + (lane >> 4) * 16;
    const uint32_t bOff = (wn + (lane & 7) + ((lane >> 4) & 1) * 8) * PITCH +
                          ((lane >> 3) & 1) * 16;

    const int g8 = lane >> 2;            // fragment row in 8-group
    const int t4 = lane & 3;             // fragment col pair

    for (int jb = 0; jb < njobs; jb++) {
        const int mode = (cta < 64) ? 0 : jmode;
        const int bi = jbi[jb];
        const int nstrips = jns[jb];
        const int total = nstrips * 16;

        const __nv_bfloat16* __restrict__ A = (mode == 2) ? g_zb2 : g_zb1;
        const __nv_bfloat16* __restrict__ B = (mode == 1) ? g_zb1 : g_zb2;
        const size_t arow0 = (size_t)bi * 128;

        // ---- issue A block load (16 slabs x 128 rows x 4 x 16B) ----
        {
            int row = tid >> 2, c16 = tid & 3;       // + it*64 rows
#pragma unroll
            for (int slab = 0; slab < 16; slab++) {
#pragma unroll
                for (int it = 0; it < 2; it++) {
                    int r = row + it * 64;
                    cp16(sdyn + slab * A_SLAB + r * PITCH + c16 * 16,
                         A + (arow0 + r) * DD + slab * 32 + c16 * 8);
                }
            }
            cp_commit();
        }

        // ---- B chunk loader ----
        auto loadB = [&](int c2) {
            int bj2 = c2 >> 4, kc = c2 & 15;
            uint32_t base = sdyn + A_TOTAL + (c2 % 3) * B_STAGE;
            int c16 = tid & 3;
#pragma unroll
            for (int it = 0; it < 4; it++) {
                int row = (tid >> 2) + it * 64;
                cp16(base + row * PITCH + c16 * 16,
                     B + ((size_t)bj2 * 256 + row) * DD + kc * 32 + c16 * 8);
            }
            cp_commit();
        };

        loadB(0);
        if (total > 1) loadB(1);

        // init row accumulator
        if (tid < 128) srow[tid] = (mode == 0) ? 0 : enc_f(-2.0f);

        float acc[4][8][4];
#pragma unroll
        for (int mi = 0; mi < 4; mi++)
#pragma unroll
            for (int ni = 0; ni < 8; ni++)
#pragma unroll
                for (int q = 0; q < 4; q++) acc[mi][ni][q] = 0.0f;

        for (int c2 = 0; c2 < total; c2++) {
            if (c2 < total - 1) cp_wait1(); else cp_wait0();
            __syncthreads();
            if (c2 + 2 < total) loadB(c2 + 2);

            const int kc = c2 & 15;
            uint32_t aBase = sdyn + kc * A_SLAB + aOff;
            uint32_t bBase = sdyn + A_TOTAL + (c2 % 3) * B_STAGE + bOff;

            uint32_t a[2][4][4], b[2][8][2];
#pragma unroll
            for (int k16 = 0; k16 < 2; k16++) {
#pragma unroll
                for (int mi = 0; mi < 4; mi++)
                    ldsm_x4(a[k16][mi], aBase + mi * 16 * PITCH + k16 * 32);
#pragma unroll
                for (int nq = 0; nq < 4; nq++) {
                    uint32_t t[4];
                    ldsm_x4(t, bBase + nq * 16 * PITCH + k16 * 32);
                    b[k16][2 * nq][0] = t[0]; b[k16][2 * nq][1] = t[1];
                    b[k16][2 * nq + 1][0] = t[2]; b[k16][2 * nq + 1][1] = t[3];
                }
            }
#pragma unroll
            for (int k16 = 0; k16 < 2; k16++)
#pragma unroll
                for (int mi = 0; mi < 4; mi++)
#pragma unroll
                    for (int ni = 0; ni < 8; ni++)
                        mma_bf16(acc[mi][ni], a[k16][mi], b[k16][ni]);

            if (kc == 15) {
                // ================= strip epilogue =================
                const int bj2 = c2 >> 4;
                const bool hasDiag = (bj2 == (bi >> 1));

                if (mode == 0) {
                    float* scf = (float*)scol;
                    float* srf = (float*)srow;
                    scf[tid] = 0.0f;
                    __syncthreads();

                    float colacc[8][2];
#pragma unroll
                    for (int ni = 0; ni < 8; ni++) { colacc[ni][0] = 0.0f; colacc[ni][1] = 0.0f; }

#pragma unroll
                    for (int mi = 0; mi < 4; mi++) {
                        int gr0 = bi * 128 + wm + mi * 16 + g8;
                        int gr1 = gr0 + 8;
                        float row0 = 0.0f, row1 = 0.0f;
#pragma unroll
                        for (int ni = 0; ni < 8; ni++) {
                            float l00 = acc[mi][ni][0] * INV_T;
                            float l01 = acc[mi][ni][1] * INV_T;
                            float l10 = acc[mi][ni][2] * INV_T;
                            float l11 = acc[mi][ni][3] * INV_T;
                            if (hasDiag) {
                                int gc0 = bj2 * 256 + wn + ni * 8 + t4 * 2;
                                if (gr0 == gc0)     g_diag[gr0] = l00;
                                if (gr0 == gc0 + 1) g_diag[gr0] = l01;
                                if (gr1 == gc0)     g_diag[gr1] = l10;
                                if (gr1 == gc0 + 1) g_diag[gr1] = l11;
                            }
                            float e00 = __expf(l00), e01 = __expf(l01);
                            float e10 = __expf(l10), e11 = __expf(l11);
                            row0 += e00 + e01;
                            row1 += e10 + e11;
                            colacc[ni][0] += e00 + e10;
                            colacc[ni][1] += e01 + e11;
                        }
                        row0 += __shfl_xor_sync(0xffffffffu, row0, 1);
                        row0 += __shfl_xor_sync(0xffffffffu, row0, 2);
                        row1 += __shfl_xor_sync(0xffffffffu, row1, 1);
                        row1 += __shfl_xor_sync(0xffffffffu, row1, 2);
                        if (t4 == 0) {
                            atomicAdd(&srf[wm + mi * 16 + g8], row0);
                            atomicAdd(&srf[wm + mi * 16 + g8 + 8], row1);
                        }
                    }
#pragma unroll
                    for (int ni = 0; ni < 8; ni++) {
#pragma unroll
                        for (int j = 0; j < 2; j++) {
                            float v = colacc[ni][j];
                            v += __shfl_xor_sync(0xffffffffu, v, 4);
                            v += __shfl_xor_sync(0xffffffffu, v, 8);
                            v += __shfl_xor_sync(0xffffffffu, v, 16);
                            if (lane < 4)
                                atomicAdd(&scf[wn + ni * 8 + (lane & 3) * 2 + j], v);
                        }
                    }
                    __syncthreads();
                    atomicAdd(&g_colsum[bj2 * 256 + tid], scf[tid]);
                } else {
                    int* __restrict__ mx = (mode == 1) ? g_max1 : g_max2;
                    scol[tid] = enc_f(-2.0f);
                    __syncthreads();

                    float colm[8][2];
#pragma unroll
                    for (int ni = 0; ni < 8; ni++) { colm[ni][0] = -2.0f; colm[ni][1] = -2.0f; }

#pragma unroll
                    for (int mi = 0; mi < 4; mi++) {
                        int gr0 = bi * 128 + wm + mi * 16 + g8;
                        int gr1 = gr0 + 8;
                        float row0 = -2.0f, row1 = -2.0f;
#pragma unroll
                        for (int ni = 0; ni < 8; ni++) {
                            float v00 = acc[mi][ni][0];
                            float v01 = acc[mi][ni][1];
                            float v10 = acc[mi][ni][2];
                            float v11 = acc[mi][ni][3];
                            if (hasDiag) {
                                int gc0 = bj2 * 256 + wn + ni * 8 + t4 * 2;
                                if (gr0 == gc0)     v00 = -2.0f;
                                if (gr0 == gc0 + 1) v01 = -2.0f;
                                if (gr1 == gc0)     v10 = -2.0f;
                                if (gr1 == gc0 + 1) v11 = -2.0f;
                            }
                            row0 = fmaxf(row0, fmaxf(v00, v01));
                            row1 = fmaxf(row1, fmaxf(v10, v11));
                            colm[ni][0] = fmaxf(colm[ni][0], fmaxf(v00, v10));
                            colm[ni][1] = fmaxf(colm[ni][1], fmaxf(v01, v11));
                        }
                        row0 = fmaxf(row0, __shfl_xor_sync(0xffffffffu, row0, 1));
                        row0 = fmaxf(row0, __shfl_xor_sync(0xffffffffu, row0, 2));
                        row1 = fmaxf(row1, __shfl_xor_sync(0xffffffffu, row1, 1));
                        row1 = fmaxf(row1, __shfl_xor_sync(0xffffffffu, row1, 2));
                        if (t4 == 0) {
                            atomicMax(&srow[wm + mi * 16 + g8], enc_f(row0));
                            atomicMax(&srow[wm + mi * 16 + g8 + 8], enc_f(row1));
                        }
                    }
#pragma unroll
                    for (int ni = 0; ni < 8; ni++) {
#pragma unroll
                        for (int j = 0; j < 2; j++) {
                            float v = colm[ni][j];
                            v = fmaxf(v, __shfl_xor_sync(0xffffffffu, v, 4));
                            v = fmaxf(v, __shfl_xor_sync(0xffffffffu, v, 8));
                            v = fmaxf(v, __shfl_xor_sync(0xffffffffu, v, 16));
                            if (lane < 4)
                                atomicMax(&scol[wn + ni * 8 + (lane & 3) * 2 + j], enc_f(v));
                        }
                    }
                    __syncthreads();
                    atomicMax(&mx[bj2 * 256 + tid], scol[tid]);
                }
                // reset accumulators for next strip
#pragma unroll
                for (int mi = 0; mi < 4; mi++)
#pragma unroll
                    for (int ni = 0; ni < 8; ni++)
#pragma unroll
                        for (int q = 0; q < 4; q++) acc[mi][ni][q] = 0.0f;
            }
        }

        // ---- job end: write row results (rows private to this CTA) ----
        __syncthreads();
        if (tid < 128) {
            if (mode == 0) {
                g_rowsum[bi * 128 + tid] = ((float*)srow)[tid];
            } else {
                int* mx = (mode == 1) ? g_max1 : g_max2;
                atomicMax(&mx[bi * 128 + tid], srow[tid]);
            }
        }
        __syncthreads();
    }
}

// ------------------- final scalar reduction (1024 threads) -------------------
__global__ void finalize_kernel(float* __restrict__ out) {
    const int t = threadIdx.x;  // 1024
    float s12 = 0.0f, s21 = 0.0f, k1 = 0.0f, k2 = 0.0f;
#pragma unroll
    for (int it = 0; it < NN / 1024; it++) {
        int i = t + it * 1024;
        float d = g_diag[i];
        s12 += logf(g_rowsum[i]) - d;
        s21 += logf(g_colsum[i]) - d;
        float m1 = dec_f(g_max1[i]);
        float m2 = dec_f(g_max2[i]);
        float d1 = sqrtf(fmaxf(2.0f - 2.0f * m1, 0.0f));
        float d2 = sqrtf(fmaxf(2.0f - 2.0f * m2, 0.0f));
        k1 += logf(d1 + EPS_KOLEO);
        k2 += logf(d2 + EPS_KOLEO);
    }
    float vals[4] = {s12, s21, k1, k2};
    __shared__ float sh[4][32];
#pragma unroll
    for (int q = 0; q < 4; q++) {
        float v = vals[q];
#pragma unroll
        for (int o = 16; o; o >>= 1) v += __shfl_xor_sync(0xffffffffu, v, o);
        if ((t & 31) == 0) sh[q][t >> 5] = v;
    }
    __syncthreads();
    if (t < 32) {
        float r[4];
#pragma unroll
        for (int q = 0; q < 4; q++) {
            float v = sh[q][t];
#pragma unroll
            for (int o = 16; o; o >>= 1) v += __shfl_xor_sync(0xffffffffu, v, o);
            r[q] = v;
        }
        if (t == 0) {
            float contrast = (r[0] + r[1]) / (2.0f * NN);
            float koleo = -(r[2] + r[3]) / (2.0f * NN);
            out[0] = contrast + 0.1f * koleo;
        }
    }
}

// ------------------- launch -------------------
extern "C" void kernel_launch(void* const* d_in, const int* in_sizes, int n_in,
                              void* d_out, int out_size) {
    const float* z1 = (const float*)d_in[0];
    const float* z2 = (const float*)d_in[1];
    float* out = (float*)d_out;

    cudaFuncSetAttribute(gemm_all, cudaFuncAttributeMaxDynamicSharedMemorySize,
                         SMEM_DYN);

    normalize_kernel<<<dim3(NN, 2), 128>>>(z1, z2);
    init_kernel<<<NN / 256, 256>>>();
    gemm_all<<<128, 256, SMEM_DYN>>>();
    finalize_kernel<<<1, 1024>>>(out);
}

// round 8
// speedup vs baseline: 1.2509x; 1.2509x over previous
#include <cuda_runtime.h>
#include <cuda_bf16.h>
#include <cstdint>

#define NN 8192
#define DD 512               // elements per row; fp8 => also bytes per row
#define INV_T 25.0f
#define EPS_KOLEO 1e-9f

// ------------------- device scratch -------------------
__device__ uint8_t g_zb1[NN * DD];   // e4m3 normalized z1
__device__ uint8_t g_zb2[NN * DD];   // e4m3 normalized z2
__device__ float g_rowsum[NN];
__device__ float g_colsum[NN];
__device__ float g_diag[NN];         // EXACT fp32 diag logits
__device__ int   g_max1[NN];
__device__ int   g_max2[NN];

// ------------------- helpers -------------------
__device__ __forceinline__ int enc_f(float f) {
    int i = __float_as_int(f);
    return i >= 0 ? i : i ^ 0x7FFFFFFF;
}
__device__ __forceinline__ float dec_f(int i) {
    return __int_as_float(i >= 0 ? i : i ^ 0x7FFFFFFF);
}
__device__ __forceinline__ uint32_t smem_u32(const void* p) {
    uint32_t a;
    asm("{ .reg .u64 t; cvta.to.shared.u64 t, %1; cvt.u32.u64 %0, t; }"
        : "=r"(a) : "l"(p));
    return a;
}
__device__ __forceinline__ void cp16(uint32_t saddr, const void* g) {
    asm volatile("cp.async.cg.shared.global [%0], [%1], 16;" :: "r"(saddr), "l"(g));
}
__device__ __forceinline__ void cp_commit() {
    asm volatile("cp.async.commit_group;" ::: "memory");
}
__device__ __forceinline__ void cp_wait1() {
    asm volatile("cp.async.wait_group 1;" ::: "memory");
}
__device__ __forceinline__ void cp_wait0() {
    asm volatile("cp.async.wait_group 0;" ::: "memory");
}
__device__ __forceinline__ void ldsm_x4(uint32_t* r, uint32_t a) {
    asm volatile("ldmatrix.sync.aligned.m8n8.x4.shared.b16 {%0,%1,%2,%3}, [%4];"
                 : "=r"(r[0]), "=r"(r[1]), "=r"(r[2]), "=r"(r[3]) : "r"(a));
}
// fp8 e4m3 MMA, m16n8k32, fp32 accum
__device__ __forceinline__ void mma_fp8(float* c, const uint32_t* a, const uint32_t* b) {
    asm volatile(
        "mma.sync.aligned.m16n8k32.row.col.f32.e4m3.e4m3.f32 "
        "{%0,%1,%2,%3}, {%4,%5,%6,%7}, {%8,%9}, {%0,%1,%2,%3};"
        : "+f"(c[0]), "+f"(c[1]), "+f"(c[2]), "+f"(c[3])
        : "r"(a[0]), "r"(a[1]), "r"(a[2]), "r"(a[3]), "r"(b[0]), "r"(b[1]));
}
// pack 4 floats -> 4 e4m3 bytes (byte0 = x)
__device__ __forceinline__ uint32_t pack_e4m3x4(float x, float y, float z, float w) {
    uint16_t lo, hi;
    asm("cvt.rn.satfinite.e4m3x2.f32 %0, %1, %2;" : "=h"(lo) : "f"(y), "f"(x));
    asm("cvt.rn.satfinite.e4m3x2.f32 %0, %1, %2;" : "=h"(hi) : "f"(w), "f"(z));
    return ((uint32_t)hi << 16) | lo;
}

// ------------------- normalization -> fp8 + exact diag -------------------
__global__ void normalize_kernel(const float* __restrict__ z1,
                                 const float* __restrict__ z2) {
    int row = blockIdx.x;
    int t = threadIdx.x;  // 128 threads x 4 floats
    float4 v1 = ((const float4*)(z1 + (size_t)row * DD))[t];
    float4 v2 = ((const float4*)(z2 + (size_t)row * DD))[t];
    float s1 = v1.x * v1.x + v1.y * v1.y + v1.z * v1.z + v1.w * v1.w;
    float s2 = v2.x * v2.x + v2.y * v2.y + v2.z * v2.z + v2.w * v2.w;
    float s12 = v1.x * v2.x + v1.y * v2.y + v1.z * v2.z + v1.w * v2.w;
#pragma unroll
    for (int o = 16; o; o >>= 1) {
        s1 += __shfl_xor_sync(0xffffffffu, s1, o);
        s2 += __shfl_xor_sync(0xffffffffu, s2, o);
        s12 += __shfl_xor_sync(0xffffffffu, s12, o);
    }
    __shared__ float ws[3][4];
    if ((t & 31) == 0) {
        ws[0][t >> 5] = s1;
        ws[1][t >> 5] = s2;
        ws[2][t >> 5] = s12;
    }
    __syncthreads();
    float t1 = ws[0][0] + ws[0][1] + ws[0][2] + ws[0][3];
    float t2 = ws[1][0] + ws[1][1] + ws[1][2] + ws[1][3];
    float t12 = ws[2][0] + ws[2][1] + ws[2][2] + ws[2][3];
    float n1 = fmaxf(sqrtf(t1), 1e-12f);
    float n2 = fmaxf(sqrtf(t2), 1e-12f);
    float sc1 = 1.0f / n1, sc2 = 1.0f / n2;
    ((uint32_t*)(g_zb1 + (size_t)row * DD))[t] =
        pack_e4m3x4(v1.x * sc1, v1.y * sc1, v1.z * sc1, v1.w * sc1);
    ((uint32_t*)(g_zb2 + (size_t)row * DD))[t] =
        pack_e4m3x4(v2.x * sc2, v2.y * sc2, v2.z * sc2, v2.w * sc2);
    if (t == 0) g_diag[row] = t12 * sc1 * sc2 * INV_T;   // exact fp32 diag logit
}

__global__ void init_kernel() {
    int i = blockIdx.x * blockDim.x + threadIdx.x;
    if (i < NN) {
        g_rowsum[i] = 0.0f;
        g_colsum[i] = 0.0f;
        int e = enc_f(-2.0f);
        g_max1[i] = e;
        g_max2[i] = e;
    }
}

// =====================================================================
// Fused FP8 HMMA GEMM, exact 1D grid:
//   t in [0,4096):      mode 0 cross (z1@z2^T): exp rowsum/colsum
//   t in [4096,6176):   mode 1 gram z1 (triangle), row/col max excl diag
//   t in [6176,8256):   mode 2 gram z2
// CTA tile 128x128, 4 warps (2x2), warp tile 64x64, BK=32 (1 fp8 k-step),
// 16 chunks, 3-stage cp.async, 2 CTAs/SM.
// smem row: 32 B data @ 48 B pitch (ldsm phases conflict-free: 12r mod 32)
// =====================================================================
#define PITCH 48
#define ST_A  (128 * PITCH)              // 6144
#define STAGE (2 * ST_A)                 // 12288
#define SMEM_DYN (3 * STAGE)             // 36864
#define NTRI  2080

__global__ __launch_bounds__(128, 2) void gemm_all() {
    int mode, bi, bj;
    {
        int t = blockIdx.x;
        if (t < 4096) {
            mode = 0; bi = t >> 6; bj = t & 63;
        } else {
            int u = t - 4096;
            mode = 1;
            if (u >= NTRI) { mode = 2; u -= NTRI; }
            int b = (int)((sqrtf((float)(8 * u + 1)) - 1.0f) * 0.5f);
            while ((b + 1) * (b + 2) / 2 <= u) b++;
            while (b * (b + 1) / 2 > u) b--;
            bi = b;
            bj = u - b * (b + 1) / 2;
        }
    }
    const bool hasDiag = (bi == bj);

    extern __shared__ __align__(16) char smem[];
    __shared__ int sred[256];

    const int tid = threadIdx.x;         // 128
    const int wid = tid >> 5;
    const int lane = tid & 31;
    const int wm = (wid >> 1) * 64;
    const int wn = (wid & 1) * 64;

    const uint8_t* __restrict__ A = (mode == 2) ? g_zb2 : g_zb1;
    const uint8_t* __restrict__ B = (mode == 1) ? g_zb1 : g_zb2;

    const size_t arow0 = (size_t)bi * 128;
    const size_t brow0 = (size_t)bj * 128;

    const uint32_t sdyn = smem_u32(smem);

    // loader: 256 A + 256 B cp16 per chunk over 128 threads
    auto load_chunk = [&](int kc, int s) {
        uint32_t base = sdyn + s * STAGE;
#pragma unroll
        for (int it = 0; it < 2; it++) {
            int f = tid + it * 128;
            int row = f >> 1, seg = f & 1;
            uint32_t off = row * PITCH + seg * 16;
            const uint8_t* gA = A + (arow0 + row) * DD + kc * 32 + seg * 16;
            const uint8_t* gB = B + (brow0 + row) * DD + kc * 32 + seg * 16;
            cp16(base + off, gA);
            cp16(base + ST_A + off, gB);
        }
        cp_commit();
    };

    float acc[4][8][4];
#pragma unroll
    for (int mi = 0; mi < 4; mi++)
#pragma unroll
        for (int ni = 0; ni < 8; ni++)
#pragma unroll
            for (int q = 0; q < 4; q++) acc[mi][ni][q] = 0.0f;

    load_chunk(0, 0);
    load_chunk(1, 1);

    // ldmatrix lane offsets (stage-relative):
    // A tiles: 0=(r0-7,k0-15) 1=(r8-15,k0-15) 2=(r0-7,k16-31) 3=(r8-15,k16-31)
    const uint32_t aOff =
        (wm + (lane & 7) + ((lane >> 3) & 1) * 8) * PITCH + ((lane >> 4) & 1) * 16;
    // B tiles: 0=(c0-7,k0-15) 1=(c0-7,k16-31) 2=(c8-15,k0-15) 3=(c8-15,k16-31)
    const uint32_t bOff = ST_A +
        (wn + (lane & 7) + ((lane >> 4) & 1) * 8) * PITCH + ((lane >> 3) & 1) * 16;

    int s = 0;
    for (int i = 0; i < 16; i++) {
        if (i < 15) cp_wait1(); else cp_wait0();
        __syncthreads();
        if (i + 2 < 16) {
            int sn = s + 2; if (sn >= 3) sn -= 3;
            load_chunk(i + 2, sn);
        }
        uint32_t stg = sdyn + s * STAGE;
        uint32_t aBase = stg + aOff;
        uint32_t bBase = stg + bOff;

        uint32_t a[4][4], b[8][2];
#pragma unroll
        for (int mi = 0; mi < 4; mi++)
            ldsm_x4(a[mi], aBase + mi * 16 * PITCH);
#pragma unroll
        for (int nq = 0; nq < 4; nq++) {
            uint32_t t[4];
            ldsm_x4(t, bBase + nq * 16 * PITCH);
            b[2 * nq][0] = t[0]; b[2 * nq][1] = t[1];
            b[2 * nq + 1][0] = t[2]; b[2 * nq + 1][1] = t[3];
        }
#pragma unroll
        for (int mi = 0; mi < 4; mi++)
#pragma unroll
            for (int ni = 0; ni < 8; ni++)
                mma_fp8(acc[mi][ni], a[mi], b[ni]);

        s++; if (s >= 3) s -= 3;
    }

    // ---------------- epilogue ----------------
    const int g = lane >> 2;
    const int t4 = lane & 3;

    if (mode == 0) {
        float* sf = (float*)sred;
        sf[tid] = 0.0f;
        sf[128 + tid] = 0.0f;
        __syncthreads();

        float colacc[8][2];
#pragma unroll
        for (int ni = 0; ni < 8; ni++) { colacc[ni][0] = 0.0f; colacc[ni][1] = 0.0f; }

#pragma unroll
        for (int mi = 0; mi < 4; mi++) {
            float row0 = 0.0f, row1 = 0.0f;
#pragma unroll
            for (int ni = 0; ni < 8; ni++) {
                float e00 = __expf(acc[mi][ni][0] * INV_T);
                float e01 = __expf(acc[mi][ni][1] * INV_T);
                float e10 = __expf(acc[mi][ni][2] * INV_T);
                float e11 = __expf(acc[mi][ni][3] * INV_T);
                row0 += e00 + e01;
                row1 += e10 + e11;
                colacc[ni][0] += e00 + e10;
                colacc[ni][1] += e01 + e11;
            }
            row0 += __shfl_xor_sync(0xffffffffu, row0, 1);
            row0 += __shfl_xor_sync(0xffffffffu, row0, 2);
            row1 += __shfl_xor_sync(0xffffffffu, row1, 1);
            row1 += __shfl_xor_sync(0xffffffffu, row1, 2);
            if (t4 == 0) {
                atomicAdd(&sf[wm + mi * 16 + g], row0);
                atomicAdd(&sf[wm + mi * 16 + g + 8], row1);
            }
        }
#pragma unroll
        for (int ni = 0; ni < 8; ni++) {
#pragma unroll
            for (int j = 0; j < 2; j++) {
                float v = colacc[ni][j];
                v += __shfl_xor_sync(0xffffffffu, v, 4);
                v += __shfl_xor_sync(0xffffffffu, v, 8);
                v += __shfl_xor_sync(0xffffffffu, v, 16);
                if (lane < 4)
                    atomicAdd(&sf[128 + wn + ni * 8 + (lane & 3) * 2 + j], v);
            }
        }
        __syncthreads();
        atomicAdd(&g_rowsum[bi * 128 + tid], sf[tid]);
        atomicAdd(&g_colsum[bj * 128 + tid], sf[128 + tid]);
    } else {
        int* __restrict__ mx = (mode == 1) ? g_max1 : g_max2;
        const int encneg = enc_f(-2.0f);
        sred[tid] = encneg;
        sred[128 + tid] = encneg;
        __syncthreads();

        float colm[8][2];
#pragma unroll
        for (int ni = 0; ni < 8; ni++) { colm[ni][0] = -2.0f; colm[ni][1] = -2.0f; }

#pragma unroll
        for (int mi = 0; mi < 4; mi++) {
            int gr0 = bi * 128 + wm + mi * 16 + g;
            int gr1 = gr0 + 8;
            float row0 = -2.0f, row1 = -2.0f;
#pragma unroll
            for (int ni = 0; ni < 8; ni++) {
                float v00 = acc[mi][ni][0];
                float v01 = acc[mi][ni][1];
                float v10 = acc[mi][ni][2];
                float v11 = acc[mi][ni][3];
                if (hasDiag) {
                    int gc0 = bj * 128 + wn + ni * 8 + t4 * 2;
                    if (gr0 == gc0)     v00 = -2.0f;
                    if (gr0 == gc0 + 1) v01 = -2.0f;
                    if (gr1 == gc0)     v10 = -2.0f;
                    if (gr1 == gc0 + 1) v11 = -2.0f;
                }
                row0 = fmaxf(row0, fmaxf(v00, v01));
                row1 = fmaxf(row1, fmaxf(v10, v11));
                colm[ni][0] = fmaxf(colm[ni][0], fmaxf(v00, v10));
                colm[ni][1] = fmaxf(colm[ni][1], fmaxf(v01, v11));
            }
            row0 = fmaxf(row0, __shfl_xor_sync(0xffffffffu, row0, 1));
            row0 = fmaxf(row0, __shfl_xor_sync(0xffffffffu, row0, 2));
            row1 = fmaxf(row1, __shfl_xor_sync(0xffffffffu, row1, 1));
            row1 = fmaxf(row1, __shfl_xor_sync(0xffffffffu, row1, 2));
            if (t4 == 0) {
                atomicMax(&sred[wm + mi * 16 + g], enc_f(row0));
                atomicMax(&sred[wm + mi * 16 + g + 8], enc_f(row1));
            }
        }
#pragma unroll
        for (int ni = 0; ni < 8; ni++) {
#pragma unroll
            for (int j = 0; j < 2; j++) {
                float v = colm[ni][j];
                v = fmaxf(v, __shfl_xor_sync(0xffffffffu, v, 4));
                v = fmaxf(v, __shfl_xor_sync(0xffffffffu, v, 8));
                v = fmaxf(v, __shfl_xor_sync(0xffffffffu, v, 16));
                if (lane < 4)
                    atomicMax(&sred[128 + wn + ni * 8 + (lane & 3) * 2 + j], enc_f(v));
            }
        }
        __syncthreads();
        atomicMax(&mx[bi * 128 + tid], sred[tid]);
        atomicMax(&mx[bj * 128 + tid], sred[128 + tid]);
    }
}

// ------------------- final scalar reduction (1024 threads) -------------------
__global__ void finalize_kernel(float* __restrict__ out) {
    const int t = threadIdx.x;  // 1024
    float s12 = 0.0f, s21 = 0.0f, k1 = 0.0f, k2 = 0.0f;
#pragma unroll
    for (int it = 0; it < NN / 1024; it++) {
        int i = t + it * 1024;
        float d = g_diag[i];
        s12 += logf(g_rowsum[i]) - d;
        s21 += logf(g_colsum[i]) - d;
        float m1 = dec_f(g_max1[i]);
        float m2 = dec_f(g_max2[i]);
        float d1 = sqrtf(fmaxf(2.0f - 2.0f * m1, 0.0f));
        float d2 = sqrtf(fmaxf(2.0f - 2.0f * m2, 0.0f));
        k1 += logf(d1 + EPS_KOLEO);
        k2 += logf(d2 + EPS_KOLEO);
    }
    float vals[4] = {s12, s21, k1, k2};
    __shared__ float sh[4][32];
#pragma unroll
    for (int q = 0; q < 4; q++) {
        float v = vals[q];
#pragma unroll
        for (int o = 16; o; o >>= 1) v += __shfl_xor_sync(0xffffffffu, v, o);
        if ((t & 31) == 0) sh[q][t >> 5] = v;
    }
    __syncthreads();
    if (t < 32) {
        float r[4];
#pragma unroll
        for (int q = 0; q < 4; q++) {
            float v = sh[q][t];
#pragma unroll
            for (int o = 16; o; o >>= 1) v += __shfl_xor_sync(0xffffffffu, v, o);
            r[q] = v;
        }
        if (t == 0) {
            float contrast = (r[0] + r[1]) / (2.0f * NN);
            float koleo = -(r[2] + r[3]) / (2.0f * NN);
            out[0] = contrast + 0.1f * koleo;
        }
    }
}

// ------------------- launch -------------------
extern "C" void kernel_launch(void* const* d_in, const int* in_sizes, int n_in,
                              void* d_out, int out_size) {
    const float* z1 = (const float*)d_in[0];
    const float* z2 = (const float*)d_in[1];
    float* out = (float*)d_out;

    cudaFuncSetAttribute(gemm_all, cudaFuncAttributeMaxDynamicSharedMemorySize,
                         SMEM_DYN);

    normalize_kernel<<<NN, 128>>>(z1, z2);
    init_kernel<<<NN / 256, 256>>>();
    gemm_all<<<4096 + 2 * NTRI, 128, SMEM_DYN>>>();
    finalize_kernel<<<1, 1024>>>(out);
}

// round 9
// speedup vs baseline: 1.3548x; 1.0830x over previous
#include <cuda_runtime.h>
#include <cuda_bf16.h>
#include <cstdint>

#define NN 8192
#define DD 512
#define INV_T 25.0f
#define EPS_KOLEO 1e-9f

// ------------------- device scratch -------------------
__device__ __nv_bfloat16 g_zb1[NN * DD];
__device__ __nv_bfloat16 g_zb2[NN * DD];
__device__ float g_rowsum[NN];
__device__ float g_colsum[NN];
__device__ float g_diag[NN];
__device__ int   g_max1[NN];
__device__ int   g_max2[NN];

// ------------------- helpers -------------------
__device__ __forceinline__ int enc_f(float f) {
    int i = __float_as_int(f);
    return i >= 0 ? i : i ^ 0x7FFFFFFF;
}
__device__ __forceinline__ float dec_f(int i) {
    return __int_as_float(i >= 0 ? i : i ^ 0x7FFFFFFF);
}
__device__ __forceinline__ uint32_t smem_u32(const void* p) {
    uint32_t a;
    asm("{ .reg .u64 t; cvta.to.shared.u64 t, %1; cvt.u32.u64 %0, t; }"
        : "=r"(a) : "l"(p));
    return a;
}
__device__ __forceinline__ void cp16(uint32_t saddr, const void* g) {
    asm volatile("cp.async.cg.shared.global [%0], [%1], 16;" :: "r"(saddr), "l"(g));
}
__device__ __forceinline__ void cp_commit() {
    asm volatile("cp.async.commit_group;" ::: "memory");
}
__device__ __forceinline__ void cp_wait1() {
    asm volatile("cp.async.wait_group 1;" ::: "memory");
}
__device__ __forceinline__ void cp_wait0() {
    asm volatile("cp.async.wait_group 0;" ::: "memory");
}
__device__ __forceinline__ void ldsm_x4(uint32_t* r, uint32_t a) {
    asm volatile("ldmatrix.sync.aligned.m8n8.x4.shared.b16 {%0,%1,%2,%3}, [%4];"
                 : "=r"(r[0]), "=r"(r[1]), "=r"(r[2]), "=r"(r[3]) : "r"(a));
}
__device__ __forceinline__ void mma_bf16(float* c, const uint32_t* a, const uint32_t* b) {
    asm volatile(
        "mma.sync.aligned.m16n8k16.row.col.f32.bf16.bf16.f32 "
        "{%0,%1,%2,%3}, {%4,%5,%6,%7}, {%8,%9}, {%0,%1,%2,%3};"
        : "+f"(c[0]), "+f"(c[1]), "+f"(c[2]), "+f"(c[3])
        : "r"(a[0]), "r"(a[1]), "r"(a[2]), "r"(a[3]), "r"(b[0]), "r"(b[1]));
}

// ------------- normalization (both matrices) + scalar init -------------
__global__ void normalize_kernel(const float* __restrict__ z1,
                                 const float* __restrict__ z2) {
    int row = blockIdx.x;
    int t = threadIdx.x;  // 128 threads x 4 floats per matrix
    float4 v1 = ((const float4*)(z1 + (size_t)row * DD))[t];
    float4 v2 = ((const float4*)(z2 + (size_t)row * DD))[t];
    float s1 = v1.x * v1.x + v1.y * v1.y + v1.z * v1.z + v1.w * v1.w;
    float s2 = v2.x * v2.x + v2.y * v2.y + v2.z * v2.z + v2.w * v2.w;
#pragma unroll
    for (int o = 16; o; o >>= 1) {
        s1 += __shfl_xor_sync(0xffffffffu, s1, o);
        s2 += __shfl_xor_sync(0xffffffffu, s2, o);
    }
    __shared__ float ws[2][4];
    if ((t & 31) == 0) {
        ws[0][t >> 5] = s1;
        ws[1][t >> 5] = s2;
    }
    __syncthreads();
    float t1 = ws[0][0] + ws[0][1] + ws[0][2] + ws[0][3];
    float t2 = ws[1][0] + ws[1][1] + ws[1][2] + ws[1][3];
    float sc1 = 1.0f / fmaxf(sqrtf(t1), 1e-12f);
    float sc2 = 1.0f / fmaxf(sqrtf(t2), 1e-12f);
    __nv_bfloat162* d1 = (__nv_bfloat162*)(g_zb1 + (size_t)row * DD);
    __nv_bfloat162* d2 = (__nv_bfloat162*)(g_zb2 + (size_t)row * DD);
    d1[t * 2 + 0] = __floats2bfloat162_rn(v1.x * sc1, v1.y * sc1);
    d1[t * 2 + 1] = __floats2bfloat162_rn(v1.z * sc1, v1.w * sc1);
    d2[t * 2 + 0] = __floats2bfloat162_rn(v2.x * sc2, v2.y * sc2);
    d2[t * 2 + 1] = __floats2bfloat162_rn(v2.z * sc2, v2.w * sc2);
    if (t == 0) {
        g_rowsum[row] = 0.0f;
        g_colsum[row] = 0.0f;
        g_diag[row] = 0.0f;
        int e = enc_f(-2.0f);
        g_max1[row] = e;
        g_max2[row] = e;
    }
}

// =====================================================================
// Fused HMMA GEMM, exact 1D grid:
//   t in [0,4096):      mode 0 cross, bi = t>>6, bj = t&63
//   t in [4096,6176):   mode 1 gram z1 (triangle decode)
//   t in [6176,8256):   mode 2 gram z2
// CTA tile 128x128, 4 warps (2x2), warp tile 64x64, BK=32, 16 chunks,
// 3-stage cp.async, one __syncthreads per chunk. 2 CTAs / SM.
// =====================================================================
#define PITCH 80                         // 64B data + 16B pad per BK row
#define ST_A  (128 * PITCH)              // 10240
#define STAGE (2 * ST_A)                 // 20480 (A + B)
#define SMEM_DYN (3 * STAGE)             // 61440
#define NTRI  2080                       // 64*65/2

__global__ __launch_bounds__(128, 2) void gemm_all() {
    int mode, bi, bj;
    {
        int t = blockIdx.x;
        if (t < 4096) {
            mode = 0; bi = t >> 6; bj = t & 63;
        } else {
            int u = t - 4096;
            mode = 1;
            if (u >= NTRI) { mode = 2; u -= NTRI; }
            int b = (int)((sqrtf((float)(8 * u + 1)) - 1.0f) * 0.5f);
            while ((b + 1) * (b + 2) / 2 <= u) b++;
            while (b * (b + 1) / 2 > u) b--;
            bi = b;
            bj = u - b * (b + 1) / 2;
        }
    }
    const bool hasDiag = (bi == bj);

    extern __shared__ __align__(16) char smem[];
    __shared__ int sred[256];            // [0:128) rows, [128:256) cols

    const int tid = threadIdx.x;         // 128
    const int wid = tid >> 5;            // 0..3
    const int lane = tid & 31;
    const int wm = (wid >> 1) * 64;
    const int wn = (wid & 1) * 64;

    const __nv_bfloat16* __restrict__ A = (mode == 2) ? g_zb2 : g_zb1;
    const __nv_bfloat16* __restrict__ B = (mode == 1) ? g_zb1 : g_zb2;

    const size_t arow0 = (size_t)bi * 128;
    const size_t brow0 = (size_t)bj * 128;

    const uint32_t sdyn = smem_u32(smem);

    const int ldrow = tid >> 2;          // 0..31 step base
    const int ldc16 = tid & 3;
    auto load_chunk = [&](int kc, int s) {
        uint32_t base = sdyn + s * STAGE;
#pragma unroll
        for (int it = 0; it < 4; it++) {
            int row = ldrow + it * 32;
            uint32_t off = row * PITCH + ldc16 * 16;
            cp16(base + off, A + (arow0 + row) * DD + kc * 32 + ldc16 * 8);
            cp16(base + ST_A + off, B + (brow0 + row) * DD + kc * 32 + ldc16 * 8);
        }
        cp_commit();
    };

    float acc[4][8][4];
#pragma unroll
    for (int mi = 0; mi < 4; mi++)
#pragma unroll
        for (int ni = 0; ni < 8; ni++)
#pragma unroll
            for (int q = 0; q < 4; q++) acc[mi][ni][q] = 0.0f;

    load_chunk(0, 0);
    load_chunk(1, 1);

    const uint32_t aOff = (wm + (lane & 15)) * PITCH + (lane >> 4) * 16;
    const uint32_t bOff = ST_A +
        (wn + (lane & 7) + ((lane >> 4) & 1) * 8) * PITCH + ((lane >> 3) & 1) * 16;

    int s = 0;
    for (int i = 0; i < 16; i++) {
        if (i < 15) cp_wait1(); else cp_wait0();
        __syncthreads();
        if (i + 2 < 16) {
            int sn = s + 2; if (sn >= 3) sn -= 3;
            load_chunk(i + 2, sn);
        }
        uint32_t stg = sdyn + s * STAGE;
        uint32_t aBase = stg + aOff;
        uint32_t bBase = stg + bOff;
#pragma unroll
        for (int k16 = 0; k16 < 2; k16++) {
            uint32_t a[4][4], b[8][2];
#pragma unroll
            for (int mi = 0; mi < 4; mi++)
                ldsm_x4(a[mi], aBase + mi * 16 * PITCH + k16 * 32);
#pragma unroll
            for (int nq = 0; nq < 4; nq++) {
                uint32_t t[4];
                ldsm_x4(t, bBase + nq * 16 * PITCH + k16 * 32);
                b[2 * nq][0] = t[0]; b[2 * nq][1] = t[1];
                b[2 * nq + 1][0] = t[2]; b[2 * nq + 1][1] = t[3];
            }
#pragma unroll
            for (int mi = 0; mi < 4; mi++)
#pragma unroll
                for (int ni = 0; ni < 8; ni++)
                    mma_bf16(acc[mi][ni], a[mi], b[ni]);
        }
        s++; if (s >= 3) s -= 3;
    }

    // ---------------- epilogue ----------------
    const int g = lane >> 2;
    const int t4 = lane & 3;

    if (mode == 0) {
        float* sf = (float*)sred;
        sf[tid] = 0.0f;
        sf[128 + tid] = 0.0f;
        __syncthreads();

        float colacc[8][2];
#pragma unroll
        for (int ni = 0; ni < 8; ni++) { colacc[ni][0] = 0.0f; colacc[ni][1] = 0.0f; }

#pragma unroll
        for (int mi = 0; mi < 4; mi++) {
            int gr0 = bi * 128 + wm + mi * 16 + g;
            int gr1 = gr0 + 8;
            float row0 = 0.0f, row1 = 0.0f;
#pragma unroll
            for (int ni = 0; ni < 8; ni++) {
                float l00 = acc[mi][ni][0] * INV_T;
                float l01 = acc[mi][ni][1] * INV_T;
                float l10 = acc[mi][ni][2] * INV_T;
                float l11 = acc[mi][ni][3] * INV_T;
                if (hasDiag) {
                    int gc0 = bj * 128 + wn + ni * 8 + t4 * 2;
                    if (gr0 == gc0)     g_diag[gr0] = l00;
                    if (gr0 == gc0 + 1) g_diag[gr0] = l01;
                    if (gr1 == gc0)     g_diag[gr1] = l10;
                    if (gr1 == gc0 + 1) g_diag[gr1] = l11;
                }
                float e00 = __expf(l00), e01 = __expf(l01);
                float e10 = __expf(l10), e11 = __expf(l11);
                row0 += e00 + e01;
                row1 += e10 + e11;
                colacc[ni][0] += e00 + e10;
                colacc[ni][1] += e01 + e11;
            }
            row0 += __shfl_xor_sync(0xffffffffu, row0, 1);
            row0 += __shfl_xor_sync(0xffffffffu, row0, 2);
            row1 += __shfl_xor_sync(0xffffffffu, row1, 1);
            row1 += __shfl_xor_sync(0xffffffffu, row1, 2);
            if (t4 == 0) {
                atomicAdd(&sf[wm + mi * 16 + g], row0);
                atomicAdd(&sf[wm + mi * 16 + g + 8], row1);
            }
        }
#pragma unroll
        for (int ni = 0; ni < 8; ni++) {
#pragma unroll
            for (int j = 0; j < 2; j++) {
                float v = colacc[ni][j];
                v += __shfl_xor_sync(0xffffffffu, v, 4);
                v += __shfl_xor_sync(0xffffffffu, v, 8);
                v += __shfl_xor_sync(0xffffffffu, v, 16);
                if (lane < 4)
                    atomicAdd(&sf[128 + wn + ni * 8 + (lane & 3) * 2 + j], v);
            }
        }
        __syncthreads();
        atomicAdd(&g_rowsum[bi * 128 + tid], sf[tid]);
        atomicAdd(&g_colsum[bj * 128 + tid], sf[128 + tid]);
    } else {
        int* __restrict__ mx = (mode == 1) ? g_max1 : g_max2;
        const int encneg = enc_f(-2.0f);
        sred[tid] = encneg;
        sred[128 + tid] = encneg;
        __syncthreads();

        float colm[8][2];
#pragma unroll
        for (int ni = 0; ni < 8; ni++) { colm[ni][0] = -2.0f; colm[ni][1] = -2.0f; }

#pragma unroll
        for (int mi = 0; mi < 4; mi++) {
            int gr0 = bi * 128 + wm + mi * 16 + g;
            int gr1 = gr0 + 8;
            float row0 = -2.0f, row1 = -2.0f;
#pragma unroll
            for (int ni = 0; ni < 8; ni++) {
                float v00 = acc[mi][ni][0];
                float v01 = acc[mi][ni][1];
                float v10 = acc[mi][ni][2];
                float v11 = acc[mi][ni][3];
                if (hasDiag) {
                    int gc0 = bj * 128 + wn + ni * 8 + t4 * 2;
                    if (gr0 == gc0)     v00 = -2.0f;
                    if (gr0 == gc0 + 1) v01 = -2.0f;
                    if (gr1 == gc0)     v10 = -2.0f;
                    if (gr1 == gc0 + 1) v11 = -2.0f;
                }
                row0 = fmaxf(row0, fmaxf(v00, v01));
                row1 = fmaxf(row1, fmaxf(v10, v11));
                colm[ni][0] = fmaxf(colm[ni][0], fmaxf(v00, v10));
                colm[ni][1] = fmaxf(colm[ni][1], fmaxf(v01, v11));
            }
            row0 = fmaxf(row0, __shfl_xor_sync(0xffffffffu, row0, 1));
            row0 = fmaxf(row0, __shfl_xor_sync(0xffffffffu, row0, 2));
            row1 = fmaxf(row1, __shfl_xor_sync(0xffffffffu, row1, 1));
            row1 = fmaxf(row1, __shfl_xor_sync(0xffffffffu, row1, 2));
            if (t4 == 0) {
                atomicMax(&sred[wm + mi * 16 + g], enc_f(row0));
                atomicMax(&sred[wm + mi * 16 + g + 8], enc_f(row1));
            }
        }
#pragma unroll
        for (int ni = 0; ni < 8; ni++) {
#pragma unroll
            for (int j = 0; j < 2; j++) {
                float v = colm[ni][j];
                v = fmaxf(v, __shfl_xor_sync(0xffffffffu, v, 4));
                v = fmaxf(v, __shfl_xor_sync(0xffffffffu, v, 8));
                v = fmaxf(v, __shfl_xor_sync(0xffffffffu, v, 16));
                if (lane < 4)
                    atomicMax(&sred[128 + wn + ni * 8 + (lane & 3) * 2 + j], enc_f(v));
            }
        }
        __syncthreads();
        atomicMax(&mx[bi * 128 + tid], sred[tid]);
        atomicMax(&mx[bj * 128 + tid], sred[128 + tid]);
    }
}

// ------------------- final scalar reduction (1024 threads) -------------------
__global__ void finalize_kernel(float* __restrict__ out) {
    const int t = threadIdx.x;  // 1024
    float s12 = 0.0f, s21 = 0.0f, k1 = 0.0f, k2 = 0.0f;
#pragma unroll
    for (int it = 0; it < NN / 1024; it++) {
        int i = t + it * 1024;
        float d = g_diag[i];
        s12 += __logf(g_rowsum[i]) - d;
        s21 += __logf(g_colsum[i]) - d;
        float m1 = dec_f(g_max1[i]);
        float m2 = dec_f(g_max2[i]);
        float d1 = sqrtf(fmaxf(2.0f - 2.0f * m1, 0.0f));
        float d2 = sqrtf(fmaxf(2.0f - 2.0f * m2, 0.0f));
        k1 += __logf(d1 + EPS_KOLEO);
        k2 += __logf(d2 + EPS_KOLEO);
    }
    float vals[4] = {s12, s21, k1, k2};
    __shared__ float sh[4][32];
#pragma unroll
    for (int q = 0; q < 4; q++) {
        float v = vals[q];
#pragma unroll
        for (int o = 16; o; o >>= 1) v += __shfl_xor_sync(0xffffffffu, v, o);
        if ((t & 31) == 0) sh[q][t >> 5] = v;
    }
    __syncthreads();
    if (t < 32) {
        float r[4];
#pragma unroll
        for (int q = 0; q < 4; q++) {
            float v = sh[q][t];
#pragma unroll
            for (int o = 16; o; o >>= 1) v += __shfl_xor_sync(0xffffffffu, v, o);
            r[q] = v;
        }
        if (t == 0) {
            float contrast = (r[0] + r[1]) / (2.0f * NN);
            float koleo = -(r[2] + r[3]) / (2.0f * NN);
            out[0] = contrast + 0.1f * koleo;
        }
    }
}

// ------------------- launch -------------------
extern "C" void kernel_launch(void* const* d_in, const int* in_sizes, int n_in,
                              void* d_out, int out_size) {
    const float* z1 = (const float*)d_in[0];
    const float* z2 = (const float*)d_in[1];
    float* out = (float*)d_out;

    cudaFuncSetAttribute(gemm_all, cudaFuncAttributeMaxDynamicSharedMemorySize,
                         SMEM_DYN);

    normalize_kernel<<<NN, 128>>>(z1, z2);
    gemm_all<<<4096 + 2 * NTRI, 128, SMEM_DYN>>>();
    finalize_kernel<<<1, 1024>>>(out);
}